// round 11
// baseline (speedup 1.0000x reference)
#include <cuda_runtime.h>

#define BATCH 524288u
#define TPB 256
#define GRID 740u            // 148 SMs x 5 resident blocks, single wave
#define STRIDE (GRID * TPB)  // 189440
typedef unsigned long long u64;

// ---- packed f32x2 primitives ----
#define F2MUL(d,a,b)    asm("mul.rn.f32x2 %0, %1, %2;" : "=l"(d) : "l"(a), "l"(b))
#define F2ADD(d,a,b)    asm("add.rn.f32x2 %0, %1, %2;" : "=l"(d) : "l"(a), "l"(b))
#define F2FMA(d,a,b,c)  asm("fma.rn.f32x2 %0, %1, %2, %3;" : "=l"(d) : "l"(a), "l"(b), "l"(c))
#define F2PACK(d,lo,hi) asm("mov.b64 %0, {%1, %2};" : "=l"(d) : "f"(lo), "f"(hi))
#define F2UNPACK(lo,hi,s) asm("mov.b64 {%0, %1}, %2;" : "=f"(lo), "=f"(hi) : "l"(s))
#define F2SWAP(d,s) asm("{\n\t.reg .b32 _l,_h;\n\tmov.b64 {_l,_h}, %1;\n\tmov.b64 %0, {_h,_l};\n\t}" : "=l"(d) : "l"(s))

#define SGNBOTH 0x8000000080000000ULL

// lane-aligned RY on pack pair: A' = c*A + sA*B ; B' = c*B + sB*oldA
__device__ __forceinline__ void ry_al(u64& AR, u64& AI, u64& BR, u64& BI,
                                      u64 c2, u64 sA, u64 sB) {
    u64 t1, t2, t3, t4, oAR = AR, oAI = AI;
    F2MUL(t1, c2, AR); F2MUL(t2, c2, AI); F2MUL(t3, c2, BR); F2MUL(t4, c2, BI);
    F2FMA(AR, sA, BR, t1);
    F2FMA(AI, sA, BI, t2);
    F2FMA(BR, sB, oAR, t3);
    F2FMA(BI, sB, oAI, t4);
}

// packed complex product: (DR,DI) = (XR,XI) lane-wise-cmul (YR,YI)
__device__ __forceinline__ void cmul2(u64& DR, u64& DI, u64 XR, u64 XI, u64 YR, u64 YI) {
    u64 m, nYI = YI ^ SGNBOTH;
    F2MUL(m, XR, YR); F2FMA(DR, XI, nYI, m);
    F2MUL(m, XR, YI); F2FMA(DI, XI, YR, m);
}

// full circuit for one sample: xv -> (Z0,Z1,Z2,Z3)
__device__ __forceinline__ float4 qbody(
    float4 xv,
    const float4* __restrict__ Kq4,     // per-qubit (cy, sy, -sy, cy)
    const float2* __restrict__ czsz,    // per-qubit (cos wz, sin wz)
    const ulonglong2* __restrict__ dRIp,
    const float4* __restrict__ r0c4, const float4* __restrict__ r1c4,
    const float4* __restrict__ r2c4, const float* __restrict__ w3c)
{
    const u64 NEG1 = 0xBF800000BF800000ULL;   // (-1.0f, -1.0f)
    float xs[4] = {xv.x, xv.y, xv.z, xv.w};

    // ---- packed prologue: per qubit F_q = lanes (u0[q], u1[q]) as (X,Y) packs ----
    u64 FX[4], FY[4];
    #pragma unroll
    for (int q = 0; q < 4; q++) {
        ulonglong2 K = reinterpret_cast<const ulonglong2*>(Kq4)[q]; // K.x=(cy,sy) K.y=(-sy,cy)
        float2 zz = czsz[q];
        float sx, cx;
        __sincosf(0.5f * xs[q], &sx, &cx);
        float t  = sx * zz.x;
        float qq = sx * zz.y;
        u64 CX, T, QQ, m;
        F2PACK(CX, cx, cx); F2PACK(T, t, t); F2PACK(QQ, qq, qq);
        F2MUL(m, K.x, CX);
        F2FMA(FX[q], K.y, T, m);    // (u0x, u1x) = (cy*cx - sy*t, sy*cx + cy*t)
        F2MUL(FY[q], K.y, QQ);      // (u0y, u1y) = (-sy*qq, cy*qq)
    }

    // ---- packed two-qubit contractions: outputs land directly in mask-12 packs ----
    // A0 = (a01[0], a01[3]) = F0 (.) F1 ; A1 = (a01[1], a01[2]) = F0 (.) swap(F1)
    u64 A0R, A0I, A1R, A1I, w1X, w1Y;
    cmul2(A0R, A0I, FX[0], FY[0], FX[1], FY[1]);
    F2SWAP(w1X, FX[1]); F2SWAP(w1Y, FY[1]);
    cmul2(A1R, A1I, FX[0], FY[0], w1X, w1Y);
    // Ba = (a23[0], a23[3]) = F2 (.) F3 ; Bb = (a23[1], a23[2]) = F2 (.) swap(F3)
    u64 BaR, BaI, BbR, BbI, w3X, w3Y;
    cmul2(BaR, BaI, FX[2], FY[2], FX[3], FY[3]);
    F2SWAP(w3X, FX[3]); F2SWAP(w3Y, FY[3]);
    cmul2(BbR, BbI, FX[2], FY[2], w3X, w3Y);

    float b0x, b3x, b0y, b3y, b1x, b2x, b1y, b2y;
    F2UNPACK(b0x, b3x, BaR); F2UNPACK(b0y, b3y, BaI);
    F2UNPACK(b1x, b2x, BbR); F2UNPACK(b1y, b2y, BbI);
    float2 a23[4] = {{b0x, b0y}, {b1x, b1y}, {b2x, b2y}, {b3x, b3y}};

    // ---- tensor product into packs along mask 12: pack p: (amp(p), amp(p^12)) ----
    u64 sR[8], sI[8];
    #pragma unroll
    for (int j = 0; j < 4; j++) {
        u64 BR, BI, nBI, t;
        F2PACK(BR, a23[j].x, a23[j].x);
        F2PACK(BI, a23[j].y, a23[j].y);
        nBI = BI ^ SGNBOTH;
        F2MUL(t, A0R, BR); F2FMA(sR[j],     A0I, nBI, t);
        F2MUL(t, A0R, BI); F2FMA(sI[j],     A0I, BR,  t);
        F2MUL(t, A1R, BR); F2FMA(sR[4 + j], A1I, nBI, t);
        F2MUL(t, A1R, BI); F2FMA(sI[4 + j], A1I, BR,  t);
    }

    // ---- fused layer-1 RZ diagonal: one LDS.128 per pack ----
    #pragma unroll
    for (int p = 0; p < 8; p++) {
        ulonglong2 dv = dRIp[p];
        u64 cR = dv.x, cI = dv.y, ncI = cI ^ SGNBOTH;
        u64 t1, t2, oR = sR[p];
        F2MUL(t1, cR, sR[p]); F2MUL(t2, cR, sI[p]);
        F2FMA(sR[p], ncI, sI[p], t1);   // Re' = cR*Re - cI*Im
        F2FMA(sI[p], cI,  oR,    t2);   // Im' = cR*Im + cI*Re
    }

    // ---- wire0 RY (in-pack cross-lane; role = par(p)) ----
    {
        ulonglong2 rv = *reinterpret_cast<const ulonglong2*>(r0c4);
        u64 c0 = rv.x, svE = rv.y, svO = svE ^ SGNBOTH;
        #pragma unroll
        for (int p = 0; p < 8; p++) {
            u64 sv = (p == 0 || p == 3 || p == 5 || p == 6) ? svE : svO;
            u64 wR, wI, t1, t2;
            F2SWAP(wR, sR[p]); F2SWAP(wI, sI[p]);
            F2MUL(t1, c0, sR[p]); F2MUL(t2, c0, sI[p]);
            F2FMA(sR[p], sv, wR, t1);
            F2FMA(sI[p], sv, wI, t2);
        }
    }
    // ---- wire1 RY (pair mask 6): pack pairs (0,6)(1,7)(2,4)(3,5) ----
    {
        ulonglong2 rv = *reinterpret_cast<const ulonglong2*>(r1c4);
        u64 c = rv.x, sA = rv.y, sB = sA ^ SGNBOTH;
        ry_al(sR[0], sI[0], sR[6], sI[6], c, sA, sB);
        ry_al(sR[1], sI[1], sR[7], sI[7], c, sA, sB);
        ry_al(sR[2], sI[2], sR[4], sI[4], c, sA, sB);
        ry_al(sR[3], sI[3], sR[5], sI[5], c, sA, sB);
    }
    // ---- wire2 RY (pair mask 3): pack pairs (0,3)(1,2)(7,4)(6,5) ----
    {
        ulonglong2 rv = *reinterpret_cast<const ulonglong2*>(r2c4);
        u64 c = rv.x, sA = rv.y, sB = sA ^ SGNBOTH;
        ry_al(sR[0], sI[0], sR[3], sI[3], c, sA, sB);
        ry_al(sR[1], sI[1], sR[2], sI[2], c, sA, sB);
        ry_al(sR[7], sI[7], sR[4], sI[4], c, sA, sB);
        ry_al(sR[6], sI[6], sR[5], sI[5], c, sA, sB);
    }

    // ---- readout with wire3 RY fused ----
    u64 P[8];
    #pragma unroll
    for (int p = 0; p < 8; p++) {
        u64 t; F2MUL(t, sR[p], sR[p]); F2FMA(P[p], sI[p], sI[p], t);
    }
    u64 CR[4];
    #pragma unroll
    for (int i = 0; i < 4; i++) {
        int p = 2 * i;
        u64 wr, wi, t;
        F2SWAP(wr, sR[p + 1]); F2SWAP(wi, sI[p + 1]);
        F2MUL(t, sR[p], wr); F2FMA(CR[i], sI[p], wi, t);
    }
    u64 sm[4], df[4];
    #pragma unroll
    for (int i = 0; i < 4; i++) {
        F2ADD(sm[i], P[2 * i], P[2 * i + 1]);
        F2FMA(df[i], P[2 * i + 1], NEG1, P[2 * i]);
    }
    u64 t1, t2, Ea, Eb, Ec, Up, Vd, g1, g2;
    F2ADD(t1, df[0], df[1]); F2ADD(t2, df[2], df[3]); F2FMA(Ea, t2, NEG1, t1); // par(p&5)
    F2ADD(t1, df[0], df[2]); F2ADD(t2, df[1], df[3]); F2FMA(Eb, t2, NEG1, t1); // par(p&3)
    F2ADD(t1, sm[0], sm[2]); F2ADD(t2, sm[1], sm[3]); F2FMA(Ec, t2, NEG1, t1); // par(p&2)
    F2FMA(g1, CR[1], NEG1, CR[0]); F2FMA(g2, CR[3], NEG1, CR[2]); F2ADD(Up, g1, g2);
    F2ADD(t1, CR[0], CR[1]); F2ADD(t2, CR[2], CR[3]); F2FMA(Vd, t2, NEG1, t1);

    float eal, eah, ebl, ebh, ecl, ech, upl, uph, vdl, vdh;
    F2UNPACK(eal, eah, Ea); F2UNPACK(ebl, ebh, Eb); F2UNPACK(ecl, ech, Ec);
    F2UNPACK(upl, uph, Up); F2UNPACK(vdl, vdh, Vd);
    float c3 = w3c[0], s3n2 = w3c[1];
    float W13 = eal + eah;   // <Z0> prob part (mask 13)
    float W5  = eal - eah;   // <Z2>           (mask 5)
    float W11 = ebl - ebh;   // <Z1>           (mask 11)
    float W10 = ecl - ech;   // <Z3> prob part (mask 10)
    float C0 = upl + uph;
    float C3 = vdl - vdh;
    float4 o;
    o.x = fmaf(c3, W13, s3n2 * C0);
    o.y = W11;
    o.z = W5;
    o.w = fmaf(c3, W10, s3n2 * C3);
    return o;
}

__global__ void __launch_bounds__(TPB, 5) quantum_layer_kernel(
    const float4* __restrict__ x, const float* __restrict__ w,
    float4* __restrict__ out)
{
    __shared__ __align__(16) float4 Kq4[4];          // per-qubit (cy, sy, -sy, cy)
    __shared__ __align__(8)  float2 czsz[4];         // per-qubit (cos wz, sin wz)
    __shared__ __align__(16) float4 dRI[8];          // diag: (cR.lo, cR.hi, cI.lo, cI.hi)
    __shared__ __align__(16) float4 r0c4, r1c4, r2c4;// RY consts: (c, c, sA.lo, sA.hi)
    __shared__ float w3c[2];                         // cos(w3), -2 sin(w3)

    int tid = threadIdx.x;
    if (tid < 4) {
        float sy, cy, sz, cz;
        __sincosf(0.5f * w[2 * tid + 1], &sy, &cy);
        __sincosf(w[2 * tid], &sz, &cz);
        Kq4[tid]  = make_float4(cy, sy, -sy, cy);
        czsz[tid] = make_float2(cz, sz);
    } else if (tid >= 16 && tid < 32) {
        // diagonal: phi(k) = sum_q (w[8+2q]/2) * (-1)^par(k & m_q), m = {7,12,14,15}
        int k = tid - 16;
        float phi = 0.5f * ( w[8]  * ((__popc(k & 7)  & 1) ? -1.f : 1.f)
                           + w[10] * ((__popc(k & 12) & 1) ? -1.f : 1.f)
                           + w[12] * ((__popc(k & 14) & 1) ? -1.f : 1.f)
                           + w[14] * ((__popc(k & 15) & 1) ? -1.f : 1.f) );
        float sp, cp; __sincosf(phi, &sp, &cp);
        int p = (k < 8) ? k : (k ^ 12);   // pack index
        int l = (k < 8) ? 0 : 1;          // lane within pack
        float* f = reinterpret_cast<float*>(dRI);
        f[4 * p + l]     = cp;            // cR lane
        f[4 * p + 2 + l] = -sp;           // cI lane (e^{-i phi} = cp - i sp)
    } else if (tid == 32) {       // wire0 RY, angle w[9]; svE = (-s, s)
        float s, c; __sincosf(0.5f * w[9], &s, &c);
        r0c4 = make_float4(c, c, -s, s);
    } else if (tid == 33) {       // wire1 RY, angle w[11]; sA = (-s,-s)
        float s, c; __sincosf(0.5f * w[11], &s, &c);
        r1c4 = make_float4(c, c, -s, -s);
    } else if (tid == 34) {       // wire2 RY, angle w[13]
        float s, c; __sincosf(0.5f * w[13], &s, &c);
        r2c4 = make_float4(c, c, -s, -s);
    } else if (tid == 35) {       // wire3 RY fused into readout: full angle w[15]
        float s, c; __sincosf(w[15], &s, &c);
        w3c[0] = c; w3c[1] = -2.f * s;
    }
    __syncthreads();

    const ulonglong2* dRIp = reinterpret_cast<const ulonglong2*>(dRI);

    // ---- exactly 2 uniform iterations + balanced per-block tail ----
    unsigned bid = blockIdx.x;
    unsigned b0 = bid * (unsigned)TPB + tid;
    unsigned b1 = b0 + STRIDE;

    // tail: samples [378880, 524288), block i gets 197 (i<368) or 196 samples
    unsigned n = (bid < 368u) ? 197u : 196u;
    unsigned tb = 2u * STRIDE + bid * 196u + min(bid, 368u) + (unsigned)tid;
    bool tact = (unsigned)tid < n;

    float4 xv = x[b0];

    // iter 0 (prefetch iter 1)
    {
        float4 cur = xv;
        xv = x[b1];
        out[b0] = qbody(cur, Kq4, czsz, dRIp, &r0c4, &r1c4, &r2c4, w3c);
    }
    // iter 1 (prefetch tail)
    {
        float4 cur = xv;
        if (tact) xv = x[tb];
        out[b1] = qbody(cur, Kq4, czsz, dRIp, &r0c4, &r1c4, &r2c4, w3c);
    }
    // tail (predicated, coalesced within block)
    if (tact) {
        out[tb] = qbody(xv, Kq4, czsz, dRIp, &r0c4, &r1c4, &r2c4, w3c);
    }
}

extern "C" void kernel_launch(void* const* d_in, const int* in_sizes, int n_in,
                              void* d_out, int out_size) {
    const float4* x = (const float4*)d_in[0];
    const float*  w = (const float*)d_in[1];
    float4* out = (float4*)d_out;
    quantum_layer_kernel<<<GRID, TPB>>>(x, w, out);
}

// round 12
// speedup vs baseline: 1.4138x; 1.4138x over previous
#include <cuda_runtime.h>

#define BATCH 524288u
#define TPB 256
#define GRID 740u            // 148 SMs x 5 resident blocks, single wave
#define STRIDE (GRID * TPB)  // 189440
typedef unsigned long long u64;

// ---- packed f32x2 primitives ----
#define F2MUL(d,a,b)    asm("mul.rn.f32x2 %0, %1, %2;" : "=l"(d) : "l"(a), "l"(b))
#define F2ADD(d,a,b)    asm("add.rn.f32x2 %0, %1, %2;" : "=l"(d) : "l"(a), "l"(b))
#define F2FMA(d,a,b,c)  asm("fma.rn.f32x2 %0, %1, %2, %3;" : "=l"(d) : "l"(a), "l"(b), "l"(c))
#define F2PACK(d,lo,hi) asm("mov.b64 %0, {%1, %2};" : "=l"(d) : "f"(lo), "f"(hi))
#define F2UNPACK(lo,hi,s) asm("mov.b64 {%0, %1}, %2;" : "=f"(lo), "=f"(hi) : "l"(s))
#define F2SWAP(d,s) asm("{\n\t.reg .b32 _l,_h;\n\tmov.b64 {_l,_h}, %1;\n\tmov.b64 %0, {_h,_l};\n\t}" : "=l"(d) : "l"(s))

#define SGNBOTH 0x8000000080000000ULL

__device__ __forceinline__ float2 cmul(float2 a, float2 b) {
    return make_float2(fmaf(a.x, b.x, -a.y * b.y), fmaf(a.x, b.y, a.y * b.x));
}

// lane-aligned RY on pack pair: A' = c*A + sA*B ; B' = c*B + sB*oldA
__device__ __forceinline__ void ry_al(u64& AR, u64& AI, u64& BR, u64& BI,
                                      u64 c2, u64 sA, u64 sB) {
    u64 t1, t2, t3, t4, oAR = AR, oAI = AI;
    F2MUL(t1, c2, AR); F2MUL(t2, c2, AI); F2MUL(t3, c2, BR); F2MUL(t4, c2, BI);
    F2FMA(AR, sA, BR, t1);
    F2FMA(AI, sA, BI, t2);
    F2FMA(BR, sB, oAR, t3);
    F2FMA(BI, sB, oAI, t4);
}

// full circuit for one sample: xv -> (Z0,Z1,Z2,Z3)
__device__ __forceinline__ float4 qbody(
    float4 xv, const float4* __restrict__ l0c,
    const ulonglong2* __restrict__ dRIp,
    const float4* __restrict__ r0c4, const float4* __restrict__ r1c4,
    const float4* __restrict__ r2c4, const float* __restrict__ w3c)
{
    const u64 NEG1 = 0xBF800000BF800000ULL;   // (-1.0f, -1.0f)
    float xs[4] = {xv.x, xv.y, xv.z, xv.w};

    // ---- prologue: RY(x) + layer-0 RZ (global phase dropped: v0 stays real) + RY ----
    float2 u0[4], u1[4];
    #pragma unroll
    for (int q = 0; q < 4; q++) {
        float4 cc = l0c[q];                   // (cy, sy, cos wz, sin wz) — one LDS.128
        float sx, cx;
        __sincosf(0.5f * xs[q], &sx, &cx);
        float t  = sx * cc.z;
        float qq = sx * cc.w;
        float m1 = cc.y * t;
        u0[q].x = fmaf(cc.x, cx, -m1);        // cy*cx - sy*sx*cos wz
        u0[q].y = -(cc.y * qq);               // -sy*sx*sin wz
        u1[q].x = fmaf(cc.y, cx, cc.x * t);   // sy*cx + cy*sx*cos wz
        u1[q].y = cc.x * qq;                  // cy*sx*sin wz
    }
    float2 a01[4], a23[4];
    a01[0] = cmul(u0[0], u0[1]); a01[1] = cmul(u0[0], u1[1]);
    a01[2] = cmul(u1[0], u0[1]); a01[3] = cmul(u1[0], u1[1]);
    a23[0] = cmul(u0[2], u0[3]); a23[1] = cmul(u0[2], u1[3]);
    a23[2] = cmul(u1[2], u0[3]); a23[3] = cmul(u1[2], u1[3]);

    // ---- tensor product into packs along mask 12: pack p: (amp(p), amp(p^12)) ----
    u64 A0R, A0I, A1R, A1I;
    F2PACK(A0R, a01[0].x, a01[3].x); F2PACK(A0I, a01[0].y, a01[3].y);
    F2PACK(A1R, a01[1].x, a01[2].x); F2PACK(A1I, a01[1].y, a01[2].y);
    u64 sR[8], sI[8];
    #pragma unroll
    for (int j = 0; j < 4; j++) {
        u64 BR, BI, nBI, t;
        F2PACK(BR, a23[j].x, a23[j].x);
        F2PACK(BI, a23[j].y, a23[j].y);
        nBI = BI ^ SGNBOTH;
        F2MUL(t, A0R, BR); F2FMA(sR[j],     A0I, nBI, t);
        F2MUL(t, A0R, BI); F2FMA(sI[j],     A0I, BR,  t);
        F2MUL(t, A1R, BR); F2FMA(sR[4 + j], A1I, nBI, t);
        F2MUL(t, A1R, BI); F2FMA(sI[4 + j], A1I, BR,  t);
    }

    // ---- fused layer-1 RZ diagonal: one LDS.128 per pack ----
    #pragma unroll
    for (int p = 0; p < 8; p++) {
        ulonglong2 dv = dRIp[p];
        u64 cR = dv.x, cI = dv.y, ncI = cI ^ SGNBOTH;
        u64 t1, t2, oR = sR[p];
        F2MUL(t1, cR, sR[p]); F2MUL(t2, cR, sI[p]);
        F2FMA(sR[p], ncI, sI[p], t1);   // Re' = cR*Re - cI*Im
        F2FMA(sI[p], cI,  oR,    t2);   // Im' = cR*Im + cI*Re
    }

    // ---- wire0 RY (in-pack cross-lane; role = par(p)) ----
    {
        ulonglong2 rv = *reinterpret_cast<const ulonglong2*>(r0c4);
        u64 c0 = rv.x, svE = rv.y, svO = svE ^ SGNBOTH;
        #pragma unroll
        for (int p = 0; p < 8; p++) {
            u64 sv = (p == 0 || p == 3 || p == 5 || p == 6) ? svE : svO;
            u64 wR, wI, t1, t2;
            F2SWAP(wR, sR[p]); F2SWAP(wI, sI[p]);
            F2MUL(t1, c0, sR[p]); F2MUL(t2, c0, sI[p]);
            F2FMA(sR[p], sv, wR, t1);
            F2FMA(sI[p], sv, wI, t2);
        }
    }
    // ---- wire1 RY (pair mask 6): pack pairs (0,6)(1,7)(2,4)(3,5) ----
    {
        ulonglong2 rv = *reinterpret_cast<const ulonglong2*>(r1c4);
        u64 c = rv.x, sA = rv.y, sB = sA ^ SGNBOTH;
        ry_al(sR[0], sI[0], sR[6], sI[6], c, sA, sB);
        ry_al(sR[1], sI[1], sR[7], sI[7], c, sA, sB);
        ry_al(sR[2], sI[2], sR[4], sI[4], c, sA, sB);
        ry_al(sR[3], sI[3], sR[5], sI[5], c, sA, sB);
    }
    // ---- wire2 RY (pair mask 3): pack pairs (0,3)(1,2)(7,4)(6,5) ----
    {
        ulonglong2 rv = *reinterpret_cast<const ulonglong2*>(r2c4);
        u64 c = rv.x, sA = rv.y, sB = sA ^ SGNBOTH;
        ry_al(sR[0], sI[0], sR[3], sI[3], c, sA, sB);
        ry_al(sR[1], sI[1], sR[2], sI[2], c, sA, sB);
        ry_al(sR[7], sI[7], sR[4], sI[4], c, sA, sB);
        ry_al(sR[6], sI[6], sR[5], sI[5], c, sA, sB);
    }

    // ---- readout with wire3 RY fused ----
    u64 P[8];
    #pragma unroll
    for (int p = 0; p < 8; p++) {
        u64 t; F2MUL(t, sR[p], sR[p]); F2FMA(P[p], sI[p], sI[p], t);
    }
    u64 CR[4];
    #pragma unroll
    for (int i = 0; i < 4; i++) {
        int p = 2 * i;
        u64 wr, wi, t;
        F2SWAP(wr, sR[p + 1]); F2SWAP(wi, sI[p + 1]);
        F2MUL(t, sR[p], wr); F2FMA(CR[i], sI[p], wi, t);
    }
    u64 sm[4], df[4];
    #pragma unroll
    for (int i = 0; i < 4; i++) {
        F2ADD(sm[i], P[2 * i], P[2 * i + 1]);
        F2FMA(df[i], P[2 * i + 1], NEG1, P[2 * i]);
    }
    u64 t1, t2, Ea, Eb, Ec, Up, Vd, g1, g2;
    F2ADD(t1, df[0], df[1]); F2ADD(t2, df[2], df[3]); F2FMA(Ea, t2, NEG1, t1); // par(p&5)
    F2ADD(t1, df[0], df[2]); F2ADD(t2, df[1], df[3]); F2FMA(Eb, t2, NEG1, t1); // par(p&3)
    F2ADD(t1, sm[0], sm[2]); F2ADD(t2, sm[1], sm[3]); F2FMA(Ec, t2, NEG1, t1); // par(p&2)
    F2FMA(g1, CR[1], NEG1, CR[0]); F2FMA(g2, CR[3], NEG1, CR[2]); F2ADD(Up, g1, g2);
    F2ADD(t1, CR[0], CR[1]); F2ADD(t2, CR[2], CR[3]); F2FMA(Vd, t2, NEG1, t1);

    float eal, eah, ebl, ebh, ecl, ech, upl, uph, vdl, vdh;
    F2UNPACK(eal, eah, Ea); F2UNPACK(ebl, ebh, Eb); F2UNPACK(ecl, ech, Ec);
    F2UNPACK(upl, uph, Up); F2UNPACK(vdl, vdh, Vd);
    float c3 = w3c[0], s3n2 = w3c[1];
    float W13 = eal + eah;   // <Z0> prob part (mask 13)
    float W5  = eal - eah;   // <Z2>           (mask 5)
    float W11 = ebl - ebh;   // <Z1>           (mask 11)
    float W10 = ecl - ech;   // <Z3> prob part (mask 10)
    float C0 = upl + uph;
    float C3 = vdl - vdh;
    float4 o;
    o.x = fmaf(c3, W13, s3n2 * C0);
    o.y = W11;
    o.z = W5;
    o.w = fmaf(c3, W10, s3n2 * C3);
    return o;
}

__global__ void __launch_bounds__(TPB, 5) quantum_layer_kernel(
    const float4* __restrict__ x, const float* __restrict__ w,
    float4* __restrict__ out)
{
    __shared__ __align__(16) float4 l0c[4];          // per-qubit (cy, sy, cos wz, sin wz)
    __shared__ __align__(16) float4 dRI[8];          // diag: (cR.lo, cR.hi, cI.lo, cI.hi)
    __shared__ __align__(16) float4 r0c4, r1c4, r2c4;// RY consts: (c, c, sA.lo, sA.hi)
    __shared__ float w3c[2];                         // cos(w3), -2 sin(w3)

    int tid = threadIdx.x;
    if (tid < 4) {
        // layer-0 per-qubit constants: half-angle RY trig, full-angle RZ trig
        float sy, cy, sz, cz;
        __sincosf(0.5f * w[2 * tid + 1], &sy, &cy);
        __sincosf(w[2 * tid], &sz, &cz);
        l0c[tid] = make_float4(cy, sy, cz, sz);
    } else if (tid >= 16 && tid < 32) {
        // diagonal: phi(k) = sum_q (w[8+2q]/2) * (-1)^par(k & m_q), m = {7,12,14,15}
        int k = tid - 16;
        float phi = 0.5f * ( w[8]  * ((__popc(k & 7)  & 1) ? -1.f : 1.f)
                           + w[10] * ((__popc(k & 12) & 1) ? -1.f : 1.f)
                           + w[12] * ((__popc(k & 14) & 1) ? -1.f : 1.f)
                           + w[14] * ((__popc(k & 15) & 1) ? -1.f : 1.f) );
        float sp, cp; __sincosf(phi, &sp, &cp);
        int p = (k < 8) ? k : (k ^ 12);   // pack index
        int l = (k < 8) ? 0 : 1;          // lane within pack
        float* f = reinterpret_cast<float*>(dRI);
        f[4 * p + l]     = cp;            // cR lane
        f[4 * p + 2 + l] = -sp;           // cI lane (e^{-i phi} = cp - i sp)
    } else if (tid == 32) {       // wire0 RY, angle w[9]; svE = (-s, s)
        float s, c; __sincosf(0.5f * w[9], &s, &c);
        r0c4 = make_float4(c, c, -s, s);
    } else if (tid == 33) {       // wire1 RY, angle w[11]; sA = (-s,-s)
        float s, c; __sincosf(0.5f * w[11], &s, &c);
        r1c4 = make_float4(c, c, -s, -s);
    } else if (tid == 34) {       // wire2 RY, angle w[13]
        float s, c; __sincosf(0.5f * w[13], &s, &c);
        r2c4 = make_float4(c, c, -s, -s);
    } else if (tid == 35) {       // wire3 RY fused into readout: full angle w[15]
        float s, c; __sincosf(w[15], &s, &c);
        w3c[0] = c; w3c[1] = -2.f * s;
    }
    __syncthreads();

    const ulonglong2* dRIp = reinterpret_cast<const ulonglong2*>(dRI);

    // ---- exactly 2 uniform iterations + balanced per-block tail ----
    unsigned bid = blockIdx.x;
    unsigned b0 = bid * (unsigned)TPB + tid;
    unsigned b1 = b0 + STRIDE;

    // tail: samples [378880, 524288), block i gets 197 (i<368) or 196 samples
    unsigned n = (bid < 368u) ? 197u : 196u;
    unsigned tb = 2u * STRIDE + bid * 196u + min(bid, 368u) + (unsigned)tid;
    bool tact = (unsigned)tid < n;

    float4 xv = x[b0];

    // iter 0 (prefetch iter 1)
    {
        float4 cur = xv;
        xv = x[b1];
        out[b0] = qbody(cur, l0c, dRIp, &r0c4, &r1c4, &r2c4, w3c);
    }
    // iter 1 (prefetch tail)
    {
        float4 cur = xv;
        if (tact) xv = x[tb];
        out[b1] = qbody(cur, l0c, dRIp, &r0c4, &r1c4, &r2c4, w3c);
    }
    // tail (predicated, coalesced within block)
    if (tact) {
        out[tb] = qbody(xv, l0c, dRIp, &r0c4, &r1c4, &r2c4, w3c);
    }
}

extern "C" void kernel_launch(void* const* d_in, const int* in_sizes, int n_in,
                              void* d_out, int out_size) {
    const float4* x = (const float4*)d_in[0];
    const float*  w = (const float*)d_in[1];
    float4* out = (float4*)d_out;
    quantum_layer_kernel<<<GRID, TPB>>>(x, w, out);
}